// round 1
// baseline (speedup 1.0000x reference)
#include <cuda_runtime.h>

#define NB 2
#define LL 256
#define HH 8
#define DD 64
#define EE 512
#define INVS 0.70710678118654752440f

// ---- scratch (static __device__, no allocations) ----
__device__ float g_W[5 * 64 * 64];        // Mqk, Mp, Wa, Wb, WvT
__device__ float g_qm[NB * LL * EE];
__device__ float g_pm[NB * LL * EE];
__device__ float g_a [NB * LL * EE];
__device__ float g_b [NB * LL * EE];
__device__ float g_vp[NB * LL * EE];
__device__ float g_base[NB * HH * LL * LL];
__device__ float g_attn[NB * HH * LL * LL];
__device__ float g_outh[NB * LL * EE];

// ---- kA0: combined 64x64 weights ----
// w=0: Mqk = Wq^T Wk ; w=1: Mp = Wpq^T Wpk ; w=2: Wa = Wq^T Wrk ; w=3: Wb = Wk^T Wrq ; w=4: WvT
__global__ void kA0(const float* __restrict__ Wq, const float* __restrict__ Wk,
                    const float* __restrict__ Wpq, const float* __restrict__ Wpk,
                    const float* __restrict__ Wrk, const float* __restrict__ Wrq,
                    const float* __restrict__ Wv) {
    int w = blockIdx.x;
    int tid = threadIdx.x;
    __shared__ float Wr[4096];
    if (w == 4) {
        for (int o = tid; o < 4096; o += 256) {
            int m = o >> 6, i = o & 63;
            g_W[4 * 4096 + o] = Wv[i * 64 + m];
        }
        return;
    }
    const float *Wl, *Wrg;
    if (w == 0)      { Wl = Wq;  Wrg = Wk;  }
    else if (w == 1) { Wl = Wpq; Wrg = Wpk; }
    else if (w == 2) { Wl = Wq;  Wrg = Wrk; }
    else             { Wl = Wk;  Wrg = Wrq; }
    for (int o = tid; o < 4096; o += 256) Wr[o] = Wrg[o];
    __syncthreads();
    int m = tid & 63, jg = tid >> 6;
    float acc[16];
#pragma unroll
    for (int j = 0; j < 16; j++) acc[j] = 0.f;
    for (int t = 0; t < 64; t++) {
        float xl = Wl[t * 64 + m];
#pragma unroll
        for (int j = 0; j < 16; j++) acc[j] = fmaf(xl, Wr[t * 64 + jg * 16 + j], acc[j]);
    }
#pragma unroll
    for (int j = 0; j < 16; j++) g_W[w * 4096 + m * 64 + jg * 16 + j] = acc[j];
}

// ---- kA: 5 fused per-head projections ----
__global__ void kA(const float* __restrict__ values, const float* __restrict__ keys,
                   const float* __restrict__ query, const float* __restrict__ pos) {
    __shared__ float xq[512], xk[512], xp[512], xv[512];
    int row = blockIdx.x;
    int t = threadIdx.x;
    xq[t] = query[row * 512 + t];
    xk[t] = keys [row * 512 + t];
    xp[t] = pos  [row * 512 + t];
    xv[t] = values[row * 512 + t];
    __syncthreads();
    int i = t & 63, hb = t & ~63;
    const float* Mqk = g_W;
    const float* Mp  = g_W + 4096;
    const float* Wa  = g_W + 8192;
    const float* Wb  = g_W + 12288;
    const float* WvT = g_W + 16384;
    float aqm = 0.f, apm = 0.f, aa = 0.f, ab = 0.f, av = 0.f;
#pragma unroll 8
    for (int m = 0; m < 64; m++) {
        float q_ = xq[hb + m], k_ = xk[hb + m], p_ = xp[hb + m], v_ = xv[hb + m];
        int wi = m * 64 + i;
        aqm = fmaf(q_, Mqk[wi], aqm);
        apm = fmaf(p_, Mp[wi],  apm);
        aa  = fmaf(q_, Wa[wi],  aa);
        ab  = fmaf(k_, Wb[wi],  ab);
        av  = fmaf(v_, WvT[wi], av);
    }
    int o = row * 512 + t;
    g_qm[o] = aqm; g_pm[o] = apm; g_a[o] = aa; g_b[o] = ab; g_vp[o] = av;
}

// ---- kB: base[n,h,q,k] = qm_q . keys_k + pm_q . pos_k ----
__global__ void kB(const float* __restrict__ keys, const float* __restrict__ pos) {
    __shared__ float Ush[2][32][64];
    __shared__ float Vsh[64][65];
    int qt = blockIdx.x, h = blockIdx.y, n = blockIdx.z;
    int tid = threadIdx.x;
#pragma unroll
    for (int ii = 0; ii < 16; ii++) {
        int flat = ii * 256 + tid;
        int src = flat >> 11;
        int q = (flat >> 6) & 31;
        int c = flat & 63;
        const float* U = src ? g_pm : g_qm;
        Ush[src][q][c] = U[(n * 256 + qt * 32 + q) * 512 + h * 64 + c];
    }
    int kid = tid & 15, qid = tid >> 4;
    for (int kt = 0; kt < 4; kt++) {
        float acc[2][4];
#pragma unroll
        for (int a = 0; a < 2; a++)
#pragma unroll
            for (int j = 0; j < 4; j++) acc[a][j] = 0.f;
        for (int src = 0; src < 2; src++) {
            __syncthreads();
            const float* V = src ? pos : keys;
#pragma unroll
            for (int ii = 0; ii < 16; ii++) {
                int flat = ii * 256 + tid;
                int k = flat >> 6;
                int c = flat & 63;
                Vsh[c][k] = V[(n * 256 + kt * 64 + k) * 512 + h * 64 + c];
            }
            __syncthreads();
#pragma unroll 4
            for (int c = 0; c < 64; c++) {
                float u0 = Ush[src][qid][c];
                float u1 = Ush[src][qid + 16][c];
#pragma unroll
                for (int j = 0; j < 4; j++) {
                    float v = Vsh[c][kid + 16 * j];
                    acc[0][j] = fmaf(u0, v, acc[0][j]);
                    acc[1][j] = fmaf(u1, v, acc[1][j]);
                }
            }
        }
#pragma unroll
        for (int a = 0; a < 2; a++)
#pragma unroll
            for (int j = 0; j < 4; j++) {
                int q = qt * 32 + qid + 16 * a;
                int k = kt * 64 + kid + 16 * j;
                g_base[((n * 8 + h) * 256 + q) * 256 + k] = acc[a][j];
            }
    }
}

// ---- kC: stream rel once; energy = (base + r.(a+b))/sqrt2 + mask; softmax ----
__global__ void kC(const float* __restrict__ rel, const float* __restrict__ mask) {
    __shared__ float a0s[512], a1s[512];
    __shared__ float eng[2][8][256];
    __shared__ float negm[256];
    int n = blockIdx.y;
    int q0 = blockIdx.x * 2;
    int tid = threadIdx.x;
    int h = tid >> 5, l = tid & 31;

    a0s[tid]       = g_a[(n * 256 + q0) * 512 + tid];
    a0s[tid + 256] = g_a[(n * 256 + q0) * 512 + 256 + tid];
    a1s[tid]       = g_a[(n * 256 + q0 + 1) * 512 + tid];
    a1s[tid + 256] = g_a[(n * 256 + q0 + 1) * 512 + 256 + tid];
    negm[tid] = (1.0f - mask[n * 256 + tid]) * -1e9f;
    __syncthreads();
#pragma unroll
    for (int ii = 0; ii < 16; ii++) {
        int flat = ii * 256 + tid;
        int qi = flat >> 11;
        int hh = (flat >> 8) & 7;
        int kk = flat & 255;
        eng[qi][hh][kk] = g_base[((n * 8 + hh) * 256 + q0 + qi) * 256 + kk] * INVS + negm[kk];
    }
    __syncthreads();

    float2 av0 = *(const float2*)&a0s[h * 64 + 2 * l];
    float2 av1 = *(const float2*)&a1s[h * 64 + 2 * l];
    const float* r0p = rel + (long)(n * 256 + q0) * 256 * 512 + h * 64 + 2 * l;
    const float* r1p = r0p + 256 * 512;
    const float* bp  = g_b + (n * 256) * 512 + h * 64 + 2 * l;

    for (int k = 0; k < 256; k += 4) {
        float2 bb[4], ra[4], rb[4];
#pragma unroll
        for (int u = 0; u < 4; u++) {
            bb[u] = *(const float2*)(bp  + (k + u) * 512);
            ra[u] = *(const float2*)(r0p + (long)(k + u) * 512);
            rb[u] = *(const float2*)(r1p + (long)(k + u) * 512);
        }
#pragma unroll
        for (int u = 0; u < 4; u++) {
            float cx = av0.x + bb[u].x, cy = av0.y + bb[u].y;
            float dx = av1.x + bb[u].x, dy = av1.y + bb[u].y;
            float s0 = ra[u].x * cx + ra[u].y * cy;
            float s1 = rb[u].x * dx + rb[u].y * dy;
#pragma unroll
            for (int off = 16; off > 0; off >>= 1) {
                s0 += __shfl_xor_sync(0xffffffffu, s0, off);
                s1 += __shfl_xor_sync(0xffffffffu, s1, off);
            }
            if (l == 0) {
                eng[0][h][k + u] += s0 * INVS;
                eng[1][h][k + u] += s1 * INVS;
            }
        }
    }
    __syncwarp();
#pragma unroll
    for (int qi = 0; qi < 2; qi++) {
        float v[8];
        float m = -1e30f;
#pragma unroll
        for (int j = 0; j < 8; j++) {
            v[j] = eng[qi][h][l + 32 * j];
            m = fmaxf(m, v[j]);
        }
#pragma unroll
        for (int off = 16; off > 0; off >>= 1)
            m = fmaxf(m, __shfl_xor_sync(0xffffffffu, m, off));
        float s = 0.f;
#pragma unroll
        for (int j = 0; j < 8; j++) {
            v[j] = __expf(v[j] - m);
            s += v[j];
        }
#pragma unroll
        for (int off = 16; off > 0; off >>= 1)
            s += __shfl_xor_sync(0xffffffffu, s, off);
        float inv = 1.0f / s;
#pragma unroll
        for (int j = 0; j < 8; j++)
            g_attn[((n * 8 + h) * 256 + q0 + qi) * 256 + l + 32 * j] = v[j] * inv;
    }
}

// ---- kD: outh[n,q,h,d] = sum_k attn[n,h,q,k] * vp[n,k,h,d] ----
__global__ void kD() {
    __shared__ float vsh[64][64];
    __shared__ float ash[32][64];
    int qt = blockIdx.x, h = blockIdx.y, n = blockIdx.z;
    int tid = threadIdx.x;
    int l = tid & 31, qid = tid >> 5;
    float acc[4][2];
#pragma unroll
    for (int a = 0; a < 4; a++) { acc[a][0] = 0.f; acc[a][1] = 0.f; }
    for (int kp = 0; kp < 4; kp++) {
        __syncthreads();
#pragma unroll
        for (int ii = 0; ii < 16; ii++) {
            int flat = ii * 256 + tid;
            int k = flat >> 6, d = flat & 63;
            vsh[k][d] = g_vp[(n * 256 + kp * 64 + k) * 512 + h * 64 + d];
        }
#pragma unroll
        for (int ii = 0; ii < 8; ii++) {
            int flat = ii * 256 + tid;
            int q = flat >> 6, k = flat & 63;
            ash[q][k] = g_attn[((n * 8 + h) * 256 + qt * 32 + q) * 256 + kp * 64 + k];
        }
        __syncthreads();
#pragma unroll 2
        for (int kk = 0; kk < 64; kk++) {
            float2 vv = *(const float2*)&vsh[kk][2 * l];
#pragma unroll
            for (int jq = 0; jq < 4; jq++) {
                float a = ash[qid + 8 * jq][kk];
                acc[jq][0] = fmaf(a, vv.x, acc[jq][0]);
                acc[jq][1] = fmaf(a, vv.y, acc[jq][1]);
            }
        }
    }
#pragma unroll
    for (int jq = 0; jq < 4; jq++) {
        int q = qt * 32 + qid + 8 * jq;
        int o = (n * 256 + q) * 512 + h * 64 + 2 * l;
        float2 r;
        r.x = acc[jq][0]; r.y = acc[jq][1];
        *(float2*)&g_outh[o] = r;
    }
}

// ---- kE: out = outh @ Wout^T + bout ----
__global__ void kE(const float* __restrict__ Wout, const float* __restrict__ bout,
                   float* __restrict__ out) {
    __shared__ float Xs[32][64];
    __shared__ float Ws[64][65];
    int rt = blockIdx.x, jt = blockIdx.y;
    int tid = threadIdx.x;
    int jid = tid & 15, rid = tid >> 4;
    float acc[2][4];
#pragma unroll
    for (int a = 0; a < 2; a++)
#pragma unroll
        for (int j = 0; j < 4; j++) acc[a][j] = 0.f;
    for (int mt = 0; mt < 8; mt++) {
        __syncthreads();
#pragma unroll
        for (int ii = 0; ii < 8; ii++) {
            int flat = ii * 256 + tid;
            int r = flat >> 6, c = flat & 63;
            Xs[r][c] = g_outh[(rt * 32 + r) * 512 + mt * 64 + c];
        }
#pragma unroll
        for (int ii = 0; ii < 16; ii++) {
            int flat = ii * 256 + tid;
            int j = flat >> 6, ml = flat & 63;
            Ws[ml][j] = Wout[(jt * 64 + j) * 512 + mt * 64 + ml];
        }
        __syncthreads();
#pragma unroll 4
        for (int ml = 0; ml < 64; ml++) {
            float u0 = Xs[rid][ml];
            float u1 = Xs[rid + 16][ml];
#pragma unroll
            for (int j4 = 0; j4 < 4; j4++) {
                float w = Ws[ml][jid + 16 * j4];
                acc[0][j4] = fmaf(u0, w, acc[0][j4]);
                acc[1][j4] = fmaf(u1, w, acc[1][j4]);
            }
        }
    }
#pragma unroll
    for (int a = 0; a < 2; a++)
#pragma unroll
        for (int j4 = 0; j4 < 4; j4++) {
            int row = rt * 32 + rid + 16 * a;
            int col = jt * 64 + jid + 16 * j4;
            out[row * 512 + col] = acc[a][j4] + bout[col];
        }
}

extern "C" void kernel_launch(void* const* d_in, const int* in_sizes, int n_in,
                              void* d_out, int out_size) {
    const float* values = (const float*)d_in[0];
    const float* keys   = (const float*)d_in[1];
    const float* query  = (const float*)d_in[2];
    const float* pos    = (const float*)d_in[3];
    const float* rel    = (const float*)d_in[4];
    const float* mask   = (const float*)d_in[5];
    const float* Wv   = (const float*)d_in[6];
    const float* Wk   = (const float*)d_in[7];
    const float* Wq   = (const float*)d_in[8];
    const float* Wpq  = (const float*)d_in[9];
    const float* Wpk  = (const float*)d_in[10];
    const float* Wrk  = (const float*)d_in[11];
    const float* Wrq  = (const float*)d_in[12];
    const float* Wout = (const float*)d_in[13];
    const float* bout = (const float*)d_in[14];
    float* out = (float*)d_out;

    kA0<<<5, 256>>>(Wq, Wk, Wpq, Wpk, Wrk, Wrq, Wv);
    kA<<<NB * LL, 512>>>(values, keys, query, pos);
    kB<<<dim3(8, HH, NB), 256>>>(keys, pos);
    kC<<<dim3(LL / 2, NB), 256>>>(rel, mask);
    kD<<<dim3(8, HH, NB), 256>>>();
    kE<<<dim3(16, 8), 256>>>(Wout, bout, out);
}

// round 2
// speedup vs baseline: 1.2173x; 1.2173x over previous
#include <cuda_runtime.h>
#include <cstdint>

#define NB 2
#define LL 256
#define HH 8
#define DD 64
#define EE 512
#define INVS 0.70710678118654752440f

// ---- scratch (static __device__, no allocations) ----
__device__ float g_W[5 * 64 * 64];        // Mqk, Mp, Wa, Wb, WvT
__device__ float g_qm[NB * LL * EE];
__device__ float g_pm[NB * LL * EE];
__device__ float g_a [NB * LL * EE];
__device__ float g_b [NB * LL * EE];
__device__ float g_vp[NB * LL * EE];
__device__ float g_base[NB * HH * LL * LL];
__device__ float g_attn[NB * HH * LL * LL];
__device__ float g_outh[NB * LL * EE];

// ---- kA0: combined 64x64 weights ----
__global__ void kA0(const float* __restrict__ Wq, const float* __restrict__ Wk,
                    const float* __restrict__ Wpq, const float* __restrict__ Wpk,
                    const float* __restrict__ Wrk, const float* __restrict__ Wrq,
                    const float* __restrict__ Wv) {
    int w = blockIdx.x;
    int tid = threadIdx.x;
    __shared__ float Wr[4096];
    if (w == 4) {
        for (int o = tid; o < 4096; o += 256) {
            int m = o >> 6, i = o & 63;
            g_W[4 * 4096 + o] = Wv[i * 64 + m];
        }
        return;
    }
    const float *Wl, *Wrg;
    if (w == 0)      { Wl = Wq;  Wrg = Wk;  }
    else if (w == 1) { Wl = Wpq; Wrg = Wpk; }
    else if (w == 2) { Wl = Wq;  Wrg = Wrk; }
    else             { Wl = Wk;  Wrg = Wrq; }
    for (int o = tid; o < 4096; o += 256) Wr[o] = Wrg[o];
    __syncthreads();
    int m = tid & 63, jg = tid >> 6;
    float acc[16];
#pragma unroll
    for (int j = 0; j < 16; j++) acc[j] = 0.f;
    for (int t = 0; t < 64; t++) {
        float xl = Wl[t * 64 + m];
#pragma unroll
        for (int j = 0; j < 16; j++) acc[j] = fmaf(xl, Wr[t * 64 + jg * 16 + j], acc[j]);
    }
#pragma unroll
    for (int j = 0; j < 16; j++) g_W[w * 4096 + m * 64 + jg * 16 + j] = acc[j];
}

// ---- kA: 5 fused per-head projections (a, b pre-scaled by 1/sqrt2) ----
__global__ void kA(const float* __restrict__ values, const float* __restrict__ keys,
                   const float* __restrict__ query, const float* __restrict__ pos) {
    __shared__ float xq[512], xk[512], xp[512], xv[512];
    int row = blockIdx.x;
    int t = threadIdx.x;
    xq[t] = query[row * 512 + t];
    xk[t] = keys [row * 512 + t];
    xp[t] = pos  [row * 512 + t];
    xv[t] = values[row * 512 + t];
    __syncthreads();
    int i = t & 63, hb = t & ~63;
    const float* Mqk = g_W;
    const float* Mp  = g_W + 4096;
    const float* Wa  = g_W + 8192;
    const float* Wb  = g_W + 12288;
    const float* WvT = g_W + 16384;
    float aqm = 0.f, apm = 0.f, aa = 0.f, ab = 0.f, av = 0.f;
#pragma unroll 8
    for (int m = 0; m < 64; m++) {
        float q_ = xq[hb + m], k_ = xk[hb + m], p_ = xp[hb + m], v_ = xv[hb + m];
        int wi = m * 64 + i;
        aqm = fmaf(q_, Mqk[wi], aqm);
        apm = fmaf(p_, Mp[wi],  apm);
        aa  = fmaf(q_, Wa[wi],  aa);
        ab  = fmaf(k_, Wb[wi],  ab);
        av  = fmaf(v_, WvT[wi], av);
    }
    int o = row * 512 + t;
    g_qm[o] = aqm; g_pm[o] = apm;
    g_a[o] = aa * INVS; g_b[o] = ab * INVS;
    g_vp[o] = av;
}

// ---- kB: base[n,h,q,k] = qm_q . keys_k + pm_q . pos_k (512 blocks) ----
__global__ void kB(const float* __restrict__ keys, const float* __restrict__ pos) {
    __shared__ float Ush[2][32][64];
    __shared__ float Vsh[64][68];
    int qt = blockIdx.x >> 2, kt = blockIdx.x & 3;
    int h = blockIdx.y, n = blockIdx.z;
    int tid = threadIdx.x;
    int kid = tid & 15, qid = tid >> 4;
#pragma unroll
    for (int ii = 0; ii < 16; ii++) {
        int flat = ii * 256 + tid;
        int src = flat >> 11;
        int q = (flat >> 6) & 31;
        int c = flat & 63;
        const float* U = src ? g_pm : g_qm;
        Ush[src][q][c] = U[(size_t)(n * 256 + qt * 32 + q) * 512 + h * 64 + c];
    }
    float acc[2][4];
#pragma unroll
    for (int a = 0; a < 2; a++)
#pragma unroll
        for (int j = 0; j < 4; j++) acc[a][j] = 0.f;
    for (int src = 0; src < 2; src++) {
        __syncthreads();
        const float* V = src ? pos : keys;
#pragma unroll
        for (int ii = 0; ii < 16; ii++) {
            int flat = ii * 256 + tid;
            int k = flat >> 6, c = flat & 63;
            Vsh[c][k] = V[(size_t)(n * 256 + kt * 64 + k) * 512 + h * 64 + c];
        }
        __syncthreads();
#pragma unroll 4
        for (int c = 0; c < 64; c++) {
            float u0 = Ush[src][qid][c];
            float u1 = Ush[src][qid + 16][c];
            float4 v4 = *(const float4*)&Vsh[c][kid * 4];
            acc[0][0] = fmaf(u0, v4.x, acc[0][0]);
            acc[0][1] = fmaf(u0, v4.y, acc[0][1]);
            acc[0][2] = fmaf(u0, v4.z, acc[0][2]);
            acc[0][3] = fmaf(u0, v4.w, acc[0][3]);
            acc[1][0] = fmaf(u1, v4.x, acc[1][0]);
            acc[1][1] = fmaf(u1, v4.y, acc[1][1]);
            acc[1][2] = fmaf(u1, v4.z, acc[1][2]);
            acc[1][3] = fmaf(u1, v4.w, acc[1][3]);
        }
    }
#pragma unroll
    for (int a = 0; a < 2; a++) {
        int q = qt * 32 + qid + 16 * a;
        float4 r;
        r.x = acc[a][0]; r.y = acc[a][1]; r.z = acc[a][2]; r.w = acc[a][3];
        *(float4*)&g_base[((size_t)((n * 8 + h) * 256 + q)) * 256 + kt * 64 + kid * 4] = r;
    }
}

// ---- kC: stream rel via cp.async; one score per lane-octet; softmax ----
__device__ __forceinline__ void cp16(uint32_t dst, const float* src) {
    asm volatile("cp.async.cg.shared.global [%0], [%1], 16;" :: "r"(dst), "l"(src));
}

__global__ void __launch_bounds__(256, 2)
kC(const float* __restrict__ rel, const float* __restrict__ mask) {
    extern __shared__ float sm[];
    float* relS = sm;                  // [2 buf][2 q][8 k][516]
    float* eng  = sm + 16512;          // [2 q][8 h][256 k]
    float* negm = sm + 20608;          // [256]
    const int n = blockIdx.y;
    const int q0 = blockIdx.x * 2;
    const int tid = threadIdx.x;
    const int w = tid >> 5, l = tid & 31;
    const int kk = l & 7, ds = l >> 3;

    negm[tid] = (1.0f - mask[n * 256 + tid]) * -1e9f;

    // preload a (already scaled by 1/sqrt2)
    float4 av[2][4];
#pragma unroll
    for (int q = 0; q < 2; q++) {
        const float4* ap = (const float4*)(g_a + (size_t)(n * 256 + q0 + q) * 512 + w * 64 + ds * 16);
#pragma unroll
        for (int u = 0; u < 4; u++) av[q][u] = ap[u];
    }
    __syncthreads();
#pragma unroll
    for (int ii = 0; ii < 16; ii++) {
        int flat = ii * 256 + tid;
        int qi = flat >> 11, hh = (flat >> 8) & 7, k2 = flat & 255;
        eng[(qi * 8 + hh) * 256 + k2] =
            g_base[((size_t)((n * 8 + hh) * 256 + q0 + qi)) * 256 + k2] * INVS + negm[k2];
    }

    uint32_t sbase = (uint32_t)__cvta_generic_to_shared(relS);
    const size_t relbase = ((size_t)(n * 256 + q0)) * 256 * 512;

    // stage tile 0
#pragma unroll
    for (int it = 0; it < 8; it++) {
        int flat = it * 256 + tid;
        int row = flat >> 7, c = flat & 127;
        int q = row >> 3, k = row & 7;
        uint32_t dst = sbase + (uint32_t)(((q) * 8 + k) * 516 + c * 4) * 4u;
        const float* src = rel + relbase + ((size_t)q * 256 + k) * 512 + c * 4;
        cp16(dst, src);
    }
    asm volatile("cp.async.commit_group;");

    for (int t = 0; t < 32; t++) {
        __syncthreads();
        if (t + 1 < 32) {
            int b2 = (t + 1) & 1;
#pragma unroll
            for (int it = 0; it < 8; it++) {
                int flat = it * 256 + tid;
                int row = flat >> 7, c = flat & 127;
                int q = row >> 3, k = row & 7;
                uint32_t dst = sbase + (uint32_t)(((b2 * 2 + q) * 8 + k) * 516 + c * 4) * 4u;
                const float* src = rel + relbase + ((size_t)q * 256 + (t + 1) * 8 + k) * 512 + c * 4;
                cp16(dst, src);
            }
            asm volatile("cp.async.commit_group;");
            asm volatile("cp.async.wait_group 1;");
        } else {
            asm volatile("cp.async.wait_group 0;");
        }
        __syncthreads();

        int b = t & 1;
        int k0 = t * 8;
        const float* r0 = relS + ((b * 2 + 0) * 8 + kk) * 516 + w * 64 + ds * 16;
        const float* r1 = relS + ((b * 2 + 1) * 8 + kk) * 516 + w * 64 + ds * 16;
        const float4* bp = (const float4*)(g_b + ((size_t)(n * 256 + k0 + kk)) * 512 + w * 64 + ds * 16);
        float s0 = 0.f, s1 = 0.f;
#pragma unroll
        for (int u = 0; u < 4; u++) {
            float4 bb = bp[u];
            float4 ra = *(const float4*)(r0 + 4 * u);
            float4 rb = *(const float4*)(r1 + 4 * u);
            float4 a0 = av[0][u], a1 = av[1][u];
            s0 = fmaf(ra.x, a0.x + bb.x, s0);
            s0 = fmaf(ra.y, a0.y + bb.y, s0);
            s0 = fmaf(ra.z, a0.z + bb.z, s0);
            s0 = fmaf(ra.w, a0.w + bb.w, s0);
            s1 = fmaf(rb.x, a1.x + bb.x, s1);
            s1 = fmaf(rb.y, a1.y + bb.y, s1);
            s1 = fmaf(rb.z, a1.z + bb.z, s1);
            s1 = fmaf(rb.w, a1.w + bb.w, s1);
        }
        s0 += __shfl_xor_sync(0xffffffffu, s0, 8);
        s0 += __shfl_xor_sync(0xffffffffu, s0, 16);
        s1 += __shfl_xor_sync(0xffffffffu, s1, 8);
        s1 += __shfl_xor_sync(0xffffffffu, s1, 16);
        if (ds == 0) {
            eng[(0 * 8 + w) * 256 + k0 + kk] += s0;
            eng[(1 * 8 + w) * 256 + k0 + kk] += s1;
        }
    }
    __syncthreads();

    // softmax: warp w handles head w, two q rows
#pragma unroll
    for (int qi = 0; qi < 2; qi++) {
        float v[8];
        float m = -1e30f;
#pragma unroll
        for (int j = 0; j < 8; j++) {
            v[j] = eng[(qi * 8 + w) * 256 + l + 32 * j];
            m = fmaxf(m, v[j]);
        }
#pragma unroll
        for (int off = 16; off > 0; off >>= 1)
            m = fmaxf(m, __shfl_xor_sync(0xffffffffu, m, off));
        float s = 0.f;
#pragma unroll
        for (int j = 0; j < 8; j++) {
            v[j] = __expf(v[j] - m);
            s += v[j];
        }
#pragma unroll
        for (int off = 16; off > 0; off >>= 1)
            s += __shfl_xor_sync(0xffffffffu, s, off);
        float inv = 1.0f / s;
#pragma unroll
        for (int j = 0; j < 8; j++)
            g_attn[((size_t)((n * 8 + w) * 256 + q0 + qi)) * 256 + l + 32 * j] = v[j] * inv;
    }
}

// ---- kD: outh[n,q,h,d] = sum_k attn[n,h,q,k] * vp[n,k,h,d] (512 thr) ----
__global__ void kD() {
    __shared__ float vsh[64][64];
    __shared__ float ash[32][64];
    int qt = blockIdx.x, h = blockIdx.y, n = blockIdx.z;
    int tid = threadIdx.x;
    int l = tid & 31, qw = tid >> 5;  // 16 warps -> 2 q each
    float acc[2][2];
    acc[0][0] = acc[0][1] = acc[1][0] = acc[1][1] = 0.f;
    for (int kp = 0; kp < 4; kp++) {
        __syncthreads();
#pragma unroll
        for (int ii = 0; ii < 8; ii++) {
            int flat = ii * 512 + tid;
            int k = flat >> 6, d = flat & 63;
            vsh[k][d] = g_vp[((size_t)(n * 256 + kp * 64 + k)) * 512 + h * 64 + d];
        }
#pragma unroll
        for (int ii = 0; ii < 4; ii++) {
            int flat = ii * 512 + tid;
            int q = flat >> 6, k = flat & 63;
            ash[q][k] = g_attn[((size_t)((n * 8 + h) * 256 + qt * 32 + q)) * 256 + kp * 64 + k];
        }
        __syncthreads();
#pragma unroll 4
        for (int kk2 = 0; kk2 < 64; kk2++) {
            float2 vv = *(const float2*)&vsh[kk2][2 * l];
            float a0 = ash[2 * qw][kk2];
            float a1 = ash[2 * qw + 1][kk2];
            acc[0][0] = fmaf(a0, vv.x, acc[0][0]);
            acc[0][1] = fmaf(a0, vv.y, acc[0][1]);
            acc[1][0] = fmaf(a1, vv.x, acc[1][0]);
            acc[1][1] = fmaf(a1, vv.y, acc[1][1]);
        }
    }
#pragma unroll
    for (int jq = 0; jq < 2; jq++) {
        int q = qt * 32 + 2 * qw + jq;
        float2 r;
        r.x = acc[jq][0]; r.y = acc[jq][1];
        *(float2*)&g_outh[((size_t)(n * 256 + q)) * 512 + h * 64 + 2 * l] = r;
    }
}

// ---- kE: out = outh @ Wout^T + bout (256 blocks, float4 tile) ----
__global__ void kE(const float* __restrict__ Wout, const float* __restrict__ bout,
                   float* __restrict__ out) {
    __shared__ float Xs[16][64];
    __shared__ float Ws[64][68];
    int rt = blockIdx.x, jt = blockIdx.y;
    int tid = threadIdx.x;
    int jid = tid & 15, rid = tid >> 4;
    float acc[4];
    acc[0] = acc[1] = acc[2] = acc[3] = 0.f;
    for (int mt = 0; mt < 8; mt++) {
        __syncthreads();
#pragma unroll
        for (int ii = 0; ii < 4; ii++) {
            int flat = ii * 256 + tid;
            int r = flat >> 6, c = flat & 63;
            Xs[r][c] = g_outh[(size_t)(rt * 16 + r) * 512 + mt * 64 + c];
        }
#pragma unroll
        for (int ii = 0; ii < 16; ii++) {
            int flat = ii * 256 + tid;
            int j = flat >> 6, ml = flat & 63;
            Ws[ml][j] = Wout[(size_t)(jt * 64 + j) * 512 + mt * 64 + ml];
        }
        __syncthreads();
#pragma unroll 8
        for (int ml = 0; ml < 64; ml++) {
            float u = Xs[rid][ml];
            float4 w4 = *(const float4*)&Ws[ml][jid * 4];
            acc[0] = fmaf(u, w4.x, acc[0]);
            acc[1] = fmaf(u, w4.y, acc[1]);
            acc[2] = fmaf(u, w4.z, acc[2]);
            acc[3] = fmaf(u, w4.w, acc[3]);
        }
    }
    int row = rt * 16 + rid;
    int col = jt * 64 + jid * 4;
    float4 bb = *(const float4*)(bout + col);
    float4 r;
    r.x = acc[0] + bb.x; r.y = acc[1] + bb.y;
    r.z = acc[2] + bb.z; r.w = acc[3] + bb.w;
    *(float4*)(out + (size_t)row * 512 + col) = r;
}

extern "C" void kernel_launch(void* const* d_in, const int* in_sizes, int n_in,
                              void* d_out, int out_size) {
    const float* values = (const float*)d_in[0];
    const float* keys   = (const float*)d_in[1];
    const float* query  = (const float*)d_in[2];
    const float* pos    = (const float*)d_in[3];
    const float* rel    = (const float*)d_in[4];
    const float* mask   = (const float*)d_in[5];
    const float* Wv   = (const float*)d_in[6];
    const float* Wk   = (const float*)d_in[7];
    const float* Wq   = (const float*)d_in[8];
    const float* Wpq  = (const float*)d_in[9];
    const float* Wpk  = (const float*)d_in[10];
    const float* Wrk  = (const float*)d_in[11];
    const float* Wrq  = (const float*)d_in[12];
    const float* Wout = (const float*)d_in[13];
    const float* bout = (const float*)d_in[14];
    float* out = (float*)d_out;

    static bool attr_done = false;
    if (!attr_done) {
        cudaFuncSetAttribute(kC, cudaFuncAttributeMaxDynamicSharedMemorySize, 84 * 1024);
        attr_done = true;
    }

    kA0<<<5, 256>>>(Wq, Wk, Wpq, Wpk, Wrk, Wrq, Wv);
    kA<<<NB * LL, 512>>>(values, keys, query, pos);
    kB<<<dim3(32, HH, NB), 256>>>(keys, pos);
    kC<<<dim3(LL / 2, NB), 256, 20864 * 4>>>(rel, mask);
    kD<<<dim3(8, HH, NB), 512>>>();
    kE<<<dim3(32, 8), 256>>>(Wout, bout, out);
}